// round 1
// baseline (speedup 1.0000x reference)
#include <cuda_runtime.h>
#include <math.h>

// Problem constants
#define BATCH   8
#define DDIM    1024
#define HWSZ    1024          // 32*32
#define NVEC    8192          // BATCH * HWSZ
#define KEMB    8192
#define Z_ELEMS 8388608       // 8*1024*32*32
#define LOSS_BLOCKS 32768     // Z_ELEMS / 256

// -------- device scratch (no allocations allowed) --------
__device__ unsigned long long g_key[NVEC];
__device__ int    g_idx[NVEC];
__device__ int    g_counts[KEMB];
__device__ float  g_sum_z2[NVEC];
__device__ float  g_sum_e2[KEMB];
__device__ double g_loss_part[LOSS_BLOCKS];

// -------- init: reset keys + counts every launch (deterministic) --------
__global__ void vq_init_kernel() {
    int i = blockIdx.x * blockDim.x + threadIdx.x;
    if (i < NVEC)  g_key[i] = 0xFFFFFFFFFFFFFFFFull;
    if (i < KEMB)  g_counts[i] = 0;
}

// -------- sum |e_k|^2 : one warp per codebook row --------
__global__ void vq_sume2_kernel(const float* __restrict__ e) {
    int warp = threadIdx.x >> 5;
    int lane = threadIdx.x & 31;
    int row  = blockIdx.x * 8 + warp;
    if (row >= KEMB) return;
    const float* p = e + (size_t)row * DDIM;
    float s = 0.f;
    #pragma unroll 4
    for (int t = lane; t < DDIM; t += 32) {
        float v = p[t];
        s = fmaf(v, v, s);
    }
    #pragma unroll
    for (int o = 16; o > 0; o >>= 1)
        s += __shfl_down_sync(0xffffffffu, s, o);
    if (lane == 0) g_sum_e2[row] = s;
}

// -------- sum |z_n|^2 : block per batch image, thread per hw, loop c --------
// z layout [b][c][h][w]; row n = b*1024 + hw gathers stride-1024 over c.
__global__ void vq_sumz2_kernel(const float* __restrict__ z) {
    int b  = blockIdx.x;
    int hw = threadIdx.x;                  // 0..1023
    const float* p = z + (size_t)b * (DDIM * HWSZ) + hw;
    float s = 0.f;
    #pragma unroll 8
    for (int c = 0; c < DDIM; c++) {
        float v = p[(size_t)c * HWSZ];
        s = fmaf(v, v, s);
    }
    g_sum_z2[b * HWSZ + hw] = s;
}

// -------- main: fused distance GEMM (fp32, sequential-d FFMA) + argmin --------
// block tile 128(n) x 128(k); 256 threads, 8x8 micro tile; D chunk = 16.
__global__ __launch_bounds__(256, 2)
void vq_dist_kernel(const float* __restrict__ z, const float* __restrict__ e) {
    __shared__ float As[16][128];
    __shared__ float Bs[16][132];
    __shared__ unsigned long long skey[128];

    const int tid = threadIdx.x;
    const int n0  = blockIdx.y * 128;
    const int k0  = blockIdx.x * 128;
    // 128 | 1024, so the n-tile lies in a single batch image
    const int b   = n0 >> 10;
    const int hw0 = n0 & 1023;
    const float* zb = z + (size_t)b * (DDIM * HWSZ) + hw0;

    const int adRow = tid >> 4;          // 0..15 (d within chunk)
    const int aCol  = (tid & 15) * 8;    // 0..120 (n within tile)
    const int bRow  = tid >> 1;          // 0..127 (k within tile)
    const int bCol  = (tid & 1) * 8;     // 0 or 8 (d within chunk)
    const int ty    = tid >> 4;          // 0..15
    const int tx    = tid & 15;          // 0..15

    float acc[8][8];
    #pragma unroll
    for (int i = 0; i < 8; i++)
        #pragma unroll
        for (int j = 0; j < 8; j++) acc[i][j] = 0.f;

    for (int dc = 0; dc < DDIM; dc += 16) {
        // global loads (coalesced float4)
        const float* pa = zb + (size_t)(dc + adRow) * HWSZ + aCol;
        float4 a0 = *(const float4*)pa;
        float4 a1 = *(const float4*)(pa + 4);
        const float* pb = e + (size_t)(k0 + bRow) * DDIM + dc + bCol;
        float4 b0 = *(const float4*)pb;
        float4 b1 = *(const float4*)(pb + 4);

        __syncthreads();   // previous chunk's compute done before overwrite
        *(float4*)&As[adRow][aCol]     = a0;
        *(float4*)&As[adRow][aCol + 4] = a1;
        Bs[bCol + 0][bRow] = b0.x;  Bs[bCol + 1][bRow] = b0.y;
        Bs[bCol + 2][bRow] = b0.z;  Bs[bCol + 3][bRow] = b0.w;
        Bs[bCol + 4][bRow] = b1.x;  Bs[bCol + 5][bRow] = b1.y;
        Bs[bCol + 6][bRow] = b1.z;  Bs[bCol + 7][bRow] = b1.w;
        __syncthreads();

        // d strictly ascending; single fp32 accumulator per (n,k) => matches
        // sequential-K FFMA accumulation (cublas-style element order)
        #pragma unroll
        for (int dd = 0; dd < 16; dd++) {
            float ar[8], br[8];
            #pragma unroll
            for (int i = 0; i < 8; i++) ar[i] = As[dd][ty * 8 + i];
            #pragma unroll
            for (int j = 0; j < 8; j++) br[j] = Bs[dd][tx * 8 + j];
            #pragma unroll
            for (int i = 0; i < 8; i++)
                #pragma unroll
                for (int j = 0; j < 8; j++)
                    acc[i][j] = fmaf(ar[i], br[j], acc[i][j]);
        }
    }

    __syncthreads();
    if (tid < 128) skey[tid] = 0xFFFFFFFFFFFFFFFFull;
    __syncthreads();

    // d = fl(fl(a + b_k) - 2*acc); FFMA contraction gives identical rounding
    // since 2*acc is exact. Key packs (d_bits, k): min key == (min d, then min k)
    // == jnp.argmin first-index tie-break (d > 0 so float bits are monotone).
    #pragma unroll
    for (int i = 0; i < 8; i++) {
        int n = n0 + ty * 8 + i;
        float a = g_sum_z2[n];
        unsigned long long best = 0xFFFFFFFFFFFFFFFFull;
        #pragma unroll
        for (int j = 0; j < 8; j++) {
            int k = k0 + tx * 8 + j;
            float t1 = a + g_sum_e2[k];
            float dv = t1 - 2.0f * acc[i][j];
            unsigned long long key =
                ((unsigned long long)__float_as_uint(dv) << 32) | (unsigned)k;
            best = (key < best) ? key : best;
        }
        atomicMin(&skey[ty * 8 + i], best);
    }
    __syncthreads();
    if (tid < 128) atomicMin(&g_key[n0 + tid], skey[tid]);
}

// -------- extract idx, build counts, optionally write idx output --------
__global__ void vq_idx_kernel(float* out_idx, int write_idx) {
    int n = blockIdx.x * blockDim.x + threadIdx.x;
    if (n >= NVEC) return;
    unsigned long long key = g_key[n];
    int idx = (int)(key & 0xFFFFFFFFull);
    g_idx[n] = idx;
    atomicAdd(&g_counts[idx], 1);
    if (write_idx) out_idx[n] = (float)idx;
}

// -------- perplexity: single block, deterministic fp64 reduction --------
__global__ void vq_perp_kernel(float* out_perp, int write) {
    __shared__ double red[1024];
    int tid = threadIdx.x;
    double s = 0.0;
    for (int t = 0; t < 8; t++) {
        int c = g_counts[tid * 8 + t];
        double p = (double)c * (1.0 / 8192.0);
        s += p * log(p + 1e-10);
    }
    red[tid] = s;
    __syncthreads();
    for (int o = 512; o > 0; o >>= 1) {
        if (tid < o) red[tid] += red[tid + o];
        __syncthreads();
    }
    if (tid == 0 && write) out_perp[0] = (float)exp(-red[0]);
}

// -------- z_q output (straight-through arithmetic replicated) + loss partials --------
__global__ void vq_out_kernel(const float* __restrict__ z,
                              const float* __restrict__ e,
                              float* __restrict__ out) {
    __shared__ double red[256];
    int i  = blockIdx.x * 256 + threadIdx.x;     // < Z_ELEMS
    int c  = (i >> 10) & 1023;
    int b  = i >> 20;
    int hw = i & 1023;
    int n  = (b << 10) | hw;
    float zq = e[(size_t)g_idx[n] * DDIM + c];
    float zv = z[i];
    float df = zq - zv;                 // fp32, as in reference
    out[i] = zv + df;                   // z + sg(z_q - z): exact op replication
    float sq = df * df;                 // fp32 square, as in reference
    red[threadIdx.x] = (double)sq;
    __syncthreads();
    for (int o = 128; o > 0; o >>= 1) {
        if (threadIdx.x < o) red[threadIdx.x] += red[threadIdx.x + o];
        __syncthreads();
    }
    if (threadIdx.x == 0) g_loss_part[blockIdx.x] = red[0];
}

// -------- finalize loss: deterministic fp64 reduce, then fp32 final ops --------
__global__ void vq_loss_kernel(float* out_loss, int write) {
    __shared__ double red[1024];
    int tid = threadIdx.x;
    double s = 0.0;
    for (int t = 0; t < LOSS_BLOCKS / 1024; t++)
        s += g_loss_part[tid * (LOSS_BLOCKS / 1024) + t];
    red[tid] = s;
    __syncthreads();
    for (int o = 512; o > 0; o >>= 1) {
        if (tid < o) red[tid] += red[tid + o];
        __syncthreads();
    }
    if (tid == 0 && write) {
        double m = red[0] / (double)Z_ELEMS;
        float mf = (float)m;
        out_loss[0] = mf + 0.25f * mf;   // mean1 + BETA*mean2 (identical means)
    }
}

extern "C" void kernel_launch(void* const* d_in, const int* in_sizes, int n_in,
                              void* d_out, int out_size) {
    const float* z = (const float*)d_in[0];
    const float* e = (const float*)d_in[1];
    float* out = (float*)d_out;

    int has_scalars = (out_size >= Z_ELEMS + 2);
    int has_idx     = (out_size >= Z_ELEMS + 2 + NVEC);

    vq_init_kernel<<<(NVEC + 255) / 256, 256>>>();
    vq_sume2_kernel<<<KEMB / 8, 256>>>(e);
    vq_sumz2_kernel<<<BATCH, 1024>>>(z);
    vq_dist_kernel<<<dim3(KEMB / 128, NVEC / 128), 256>>>(z, e);
    vq_idx_kernel<<<(NVEC + 255) / 256, 256>>>(
        has_idx ? out + Z_ELEMS + 2 : (float*)d_out, has_idx);
    vq_perp_kernel<<<1, 1024>>>(
        has_scalars ? out + Z_ELEMS + 1 : (float*)d_out, has_scalars);
    vq_out_kernel<<<LOSS_BLOCKS, 256>>>(z, e, out);
    vq_loss_kernel<<<1, 1024>>>(
        has_scalars ? out + Z_ELEMS : (float*)d_out, has_scalars);
}

// round 2
// speedup vs baseline: 1.2257x; 1.2257x over previous
#include <cuda_runtime.h>
#include <math.h>

// Problem constants
#define BATCH   8
#define DDIM    1024
#define HWSZ    1024          // 32*32
#define NVEC    8192          // BATCH * HWSZ
#define KEMB    8192
#define Z_ELEMS 8388608       // 8*1024*32*32
#define OUT_BLOCKS 4096       // vq_out grid (grid-stride)

// -------- device scratch (no allocations allowed) --------
__device__ unsigned long long g_key[NVEC];
__device__ int    g_idx[NVEC];
__device__ int    g_counts[KEMB];
__device__ float  g_sum_z2[NVEC];
__device__ float  g_sum_e2[KEMB];
__device__ double g_loss_part[OUT_BLOCKS];

// -------- init: reset keys + counts every launch (deterministic) --------
__global__ void vq_init_kernel() {
    int i = blockIdx.x * blockDim.x + threadIdx.x;
    if (i < NVEC)  g_key[i] = 0xFFFFFFFFFFFFFFFFull;
    if (i < KEMB)  g_counts[i] = 0;
}

// -------- sum |e_k|^2 : one warp per codebook row --------
__global__ void vq_sume2_kernel(const float* __restrict__ e) {
    int warp = threadIdx.x >> 5;
    int lane = threadIdx.x & 31;
    int row  = blockIdx.x * 8 + warp;
    if (row >= KEMB) return;
    const float* p = e + (size_t)row * DDIM;
    float s = 0.f;
    #pragma unroll 4
    for (int t = lane; t < DDIM; t += 32) {
        float v = p[t];
        s = fmaf(v, v, s);
    }
    #pragma unroll
    for (int o = 16; o > 0; o >>= 1)
        s += __shfl_down_sync(0xffffffffu, s, o);
    if (lane == 0) g_sum_e2[row] = s;
}

// -------- sum |z_n|^2 --------
__global__ void vq_sumz2_kernel(const float* __restrict__ z) {
    int b  = blockIdx.x;
    int hw = threadIdx.x;                  // 0..1023
    const float* p = z + (size_t)b * (DDIM * HWSZ) + hw;
    float s = 0.f;
    #pragma unroll 8
    for (int c = 0; c < DDIM; c++) {
        float v = p[(size_t)c * HWSZ];
        s = fmaf(v, v, s);
    }
    g_sum_z2[b * HWSZ + hw] = s;
}

// -------- main: fused distance GEMM (fp32, sequential-d FFMA) + argmin --------
// block tile 128(n) x 128(k); 256 threads; warp layout 2x4 (64n x 32k warp
// tile); lane layout 8x4; 8x8 micro tile; BK=8; double-buffered smem;
// all fragment loads LDS.128.
__global__ __launch_bounds__(256, 2)
void vq_dist_kernel(const float* __restrict__ z, const float* __restrict__ e) {
    __shared__ float As[2][8][128];
    __shared__ float Bs[2][8][128];
    __shared__ unsigned long long skey[128];

    const int tid  = threadIdx.x;
    const int warp = tid >> 5;
    const int lane = tid & 31;
    const int n0   = blockIdx.y * 128;
    const int k0   = blockIdx.x * 128;
    // 128 | 1024 => n-tile lies inside one batch image
    const int b    = n0 >> 10;
    const int hw0  = n0 & 1023;
    const float* zb = z + (size_t)b * (DDIM * HWSZ) + hw0;

    // global-load mapping
    const int aRow = tid >> 5;            // 0..7  (d within chunk)
    const int aCol = (tid & 31) * 4;      // 0..124 (n), float4
    const int bRow = tid >> 1;            // 0..127 (k)
    const int bOff = (tid & 1) * 4;       // 0 or 4 (d within chunk), float4

    // compute mapping: warp tile 64(n) x 32(k)
    const int nb = (warp & 1) * 64 + (lane >> 2) * 8;   // n base in tile
    const int kb = (warp >> 1) * 32 + (lane & 3) * 8;   // k base in tile

    if (tid < 128) skey[tid] = 0xFFFFFFFFFFFFFFFFull;

    float acc[8][8];
    #pragma unroll
    for (int i = 0; i < 8; i++)
        #pragma unroll
        for (int j = 0; j < 8; j++) acc[i][j] = 0.f;

    // prologue: load chunk 0 into buffer 0
    float4 aL = *(const float4*)(zb + (size_t)aRow * HWSZ + aCol);
    float4 bL = *(const float4*)(e + (size_t)(k0 + bRow) * DDIM + bOff);
    *(float4*)&As[0][aRow][aCol] = aL;
    Bs[0][bOff + 0][bRow] = bL.x;
    Bs[0][bOff + 1][bRow] = bL.y;
    Bs[0][bOff + 2][bRow] = bL.z;
    Bs[0][bOff + 3][bRow] = bL.w;
    __syncthreads();

    int buf = 0;
    #pragma unroll 1
    for (int dc = 8; dc <= DDIM; dc += 8) {
        if (dc < DDIM) {
            aL = *(const float4*)(zb + (size_t)(dc + aRow) * HWSZ + aCol);
            bL = *(const float4*)(e + (size_t)(k0 + bRow) * DDIM + dc + bOff);
        }
        // compute current buffer: d strictly ascending, single accumulator
        #pragma unroll
        for (int dd = 0; dd < 8; dd++) {
            float4 a0 = *(const float4*)&As[buf][dd][nb];
            float4 a1 = *(const float4*)&As[buf][dd][nb + 4];
            float4 b0 = *(const float4*)&Bs[buf][dd][kb];
            float4 b1 = *(const float4*)&Bs[buf][dd][kb + 4];
            float ar[8] = {a0.x, a0.y, a0.z, a0.w, a1.x, a1.y, a1.z, a1.w};
            float br[8] = {b0.x, b0.y, b0.z, b0.w, b1.x, b1.y, b1.z, b1.w};
            #pragma unroll
            for (int i = 0; i < 8; i++)
                #pragma unroll
                for (int j = 0; j < 8; j++)
                    acc[i][j] = fmaf(ar[i], br[j], acc[i][j]);
        }
        if (dc < DDIM) {
            // safe: prior readers of buf^1 finished before last __syncthreads()
            *(float4*)&As[buf ^ 1][aRow][aCol] = aL;
            Bs[buf ^ 1][bOff + 0][bRow] = bL.x;
            Bs[buf ^ 1][bOff + 1][bRow] = bL.y;
            Bs[buf ^ 1][bOff + 2][bRow] = bL.z;
            Bs[buf ^ 1][bOff + 3][bRow] = bL.w;
            __syncthreads();
            buf ^= 1;
        }
    }

    __syncthreads();   // skey init + all compute done

    // d = fl(fl(a + b_k) - 2*acc); FFMA contraction safe (2*acc exact).
    // Packed key (d_bits, k): min key == (min d, then min k) == jnp.argmin.
    #pragma unroll
    for (int i = 0; i < 8; i++) {
        int n = n0 + nb + i;
        float a = g_sum_z2[n];
        unsigned long long best = 0xFFFFFFFFFFFFFFFFull;
        #pragma unroll
        for (int j = 0; j < 8; j++) {
            int k = k0 + kb + j;
            float t1 = a + g_sum_e2[k];
            float dv = t1 - 2.0f * acc[i][j];
            unsigned long long key =
                ((unsigned long long)__float_as_uint(dv) << 32) | (unsigned)k;
            best = (key < best) ? key : best;
        }
        atomicMin(&skey[nb + i], best);
    }
    __syncthreads();
    if (tid < 128) atomicMin(&g_key[n0 + tid], skey[tid]);
}

// -------- extract idx, build counts, optionally write idx output --------
__global__ void vq_idx_kernel(float* out_idx, int write_idx) {
    int n = blockIdx.x * blockDim.x + threadIdx.x;
    if (n >= NVEC) return;
    unsigned long long key = g_key[n];
    int idx = (int)(key & 0xFFFFFFFFull);
    g_idx[n] = idx;
    atomicAdd(&g_counts[idx], 1);
    if (write_idx) out_idx[n] = (float)idx;
}

// -------- perplexity: single block, deterministic fp64 reduction --------
__global__ void vq_perp_kernel(float* out_perp, int write) {
    __shared__ double red[1024];
    int tid = threadIdx.x;
    double s = 0.0;
    for (int t = 0; t < 8; t++) {
        int c = g_counts[tid * 8 + t];
        double p = (double)c * (1.0 / 8192.0);
        s += p * log(p + 1e-10);
    }
    red[tid] = s;
    __syncthreads();
    for (int o = 512; o > 0; o >>= 1) {
        if (tid < o) red[tid] += red[tid + o];
        __syncthreads();
    }
    if (tid == 0 && write) out_perp[0] = (float)exp(-red[0]);
}

// -------- z_q output (STE arithmetic replicated) + loss partials --------
__global__ void vq_out_kernel(const float* __restrict__ z,
                              const float* __restrict__ e,
                              float* __restrict__ out) {
    __shared__ double red[256];
    double acc = 0.0;
    #pragma unroll 1
    for (int i = blockIdx.x * 256 + threadIdx.x; i < Z_ELEMS;
         i += OUT_BLOCKS * 256) {
        int c  = (i >> 10) & 1023;
        int b  = i >> 20;
        int hw = i & 1023;
        int n  = (b << 10) | hw;
        float zq = e[(size_t)g_idx[n] * DDIM + c];
        float zv = z[i];
        float df = zq - zv;              // fp32, as in reference
        out[i] = zv + df;                // z + sg(z_q - z)
        float sq = df * df;              // fp32 square, as in reference
        acc += (double)sq;
    }
    red[threadIdx.x] = acc;
    __syncthreads();
    for (int o = 128; o > 0; o >>= 1) {
        if (threadIdx.x < o) red[threadIdx.x] += red[threadIdx.x + o];
        __syncthreads();
    }
    if (threadIdx.x == 0) g_loss_part[blockIdx.x] = red[0];
}

// -------- finalize loss --------
__global__ void vq_loss_kernel(float* out_loss, int write) {
    __shared__ double red[1024];
    int tid = threadIdx.x;
    double s = 0.0;
    for (int t = 0; t < OUT_BLOCKS / 1024; t++)
        s += g_loss_part[tid * (OUT_BLOCKS / 1024) + t];
    red[tid] = s;
    __syncthreads();
    for (int o = 512; o > 0; o >>= 1) {
        if (tid < o) red[tid] += red[tid + o];
        __syncthreads();
    }
    if (tid == 0 && write) {
        double m = red[0] / (double)Z_ELEMS;
        float mf = (float)m;
        out_loss[0] = mf + 0.25f * mf;   // mean1 + BETA*mean2 (identical means)
    }
}

extern "C" void kernel_launch(void* const* d_in, const int* in_sizes, int n_in,
                              void* d_out, int out_size) {
    const float* z = (const float*)d_in[0];
    const float* e = (const float*)d_in[1];
    float* out = (float*)d_out;

    int has_scalars = (out_size >= Z_ELEMS + 2);
    int has_idx     = (out_size >= Z_ELEMS + 2 + NVEC);

    vq_init_kernel<<<(NVEC + 255) / 256, 256>>>();
    vq_sume2_kernel<<<KEMB / 8, 256>>>(e);
    vq_sumz2_kernel<<<BATCH, 1024>>>(z);
    vq_dist_kernel<<<dim3(KEMB / 128, NVEC / 128), 256>>>(z, e);
    vq_idx_kernel<<<(NVEC + 255) / 256, 256>>>(
        has_idx ? out + Z_ELEMS + 2 : (float*)d_out, has_idx);
    vq_perp_kernel<<<1, 1024>>>(
        has_scalars ? out + Z_ELEMS + 1 : (float*)d_out, has_scalars);
    vq_out_kernel<<<OUT_BLOCKS, 256>>>(z, e, out);
    vq_loss_kernel<<<1, 1024>>>(
        has_scalars ? out + Z_ELEMS : (float*)d_out, has_scalars);
}